// round 11
// baseline (speedup 1.0000x reference)
#include <cuda_runtime.h>

#define C 100
#define D 128
#define EPSF 1e-8f
#define NG 4                 // classes per pass1 block (== warps per block)
#define GRPS (C / NG)        // 25 class-groups
#define CHUNKS 80            // sample chunks -> grid = 2000
#define TILE 4096            // labels scanned per queue/drain cycle
#define QCAP 768             // per-class queue capacity (E=41/cycle)

// ---------------- device scratch (allocation-free) ----------------
__device__ float g_sums[C * D];
__device__ float g_counts[C];
__device__ float g_spreadsum[C];
__device__ float g_cent[C * D];
__device__ float g_centN[C * D];
__device__ float g_sims[C * C];

// ---------------- zero scratch ----------------
__global__ void zero_kernel() {
    int i = blockIdx.x * blockDim.x + threadIdx.x;
    if (i < C * D) g_sums[i] = 0.f;
    if (i < C) { g_counts[i] = 0.f; g_spreadsum[i] = 0.f; }
}

// ---------------- pass 1: queue-then-gather, MLP=8 ----------------
// Phase A: scan TILE labels, warp-aggregated append of matching row indices
// into NG per-class smem queues. Phase B: warp w drains class w's queue in
// unrolled groups of 8 -> 8 independent LDG.128 with DISTINCT register sets
// (MLP=8; the old ffs-walk had a WAR hazard forcing MLP=1). Accumulate in a
// single float4/lane register; flush = 4 atomicAdd warp-instructions.
__global__ void __launch_bounds__(128) pass1_kernel(
    const float* __restrict__ emb, const int* __restrict__ labels, int N) {
    __shared__ int queue[NG][QCAP];
    __shared__ int qcnt[NG];
    const int t = threadIdx.x, w = t >> 5, lane = t & 31;
    const int grp = blockIdx.x % GRPS;   // consecutive bids share a chunk
    const int chunk = blockIdx.x / GRPS; // -> label range stays L2-hot
    const int cls0 = grp * NG;
    const int n_per = (N + CHUNKS - 1) / CHUNKS;
    const int start = chunk * n_per;
    const int end = min(start + n_per, N);

    float4 acc = make_float4(0.f, 0.f, 0.f, 0.f);  // class cls0+w (this warp)
    float cnt = 0.f;

    for (int tstart = start; tstart < end; tstart += TILE) {
        const int tend = min(tstart + TILE, end);
        if (t < NG) qcnt[t] = 0;
        __syncthreads();

        // ---- Phase A: scan & append ----
        for (int b = tstart + w * 32; b < tend; b += 128) {
            int idx = b + lane;
            int lab = (idx < tend) ? labels[idx] : -1;
#pragma unroll
            for (int g = 0; g < NG; g++) {
                bool pred = (lab == cls0 + g);
                unsigned m = __ballot_sync(0xffffffffu, pred);
                if (m) {
                    int leader = __ffs(m) - 1;
                    int nmatch = __popc(m);
                    int base = 0;
                    if (lane == leader) base = atomicAdd(&qcnt[g], nmatch);
                    base = __shfl_sync(0xffffffffu, base, leader);
                    int prefix = __popc(m & ((1u << lane) - 1u));
                    int pos = base + prefix;
                    if (pred && pos < QCAP) queue[g][pos] = idx;
                }
            }
        }
        __syncthreads();

        // ---- Phase B: drain class w with MLP=8 ----
        int qn = min(qcnt[w], QCAP);
        cnt += (lane == 0) ? (float)qn : 0.f;
        for (int i = 0; i < qn; i += 8) {
            int r[8];
#pragma unroll
            for (int k = 0; k < 8; k++)
                r[k] = (i + k < qn) ? queue[w][i + k] : -1;
            float4 e[8];
#pragma unroll
            for (int k = 0; k < 8; k++) {
                if (r[k] >= 0)
                    e[k] = *reinterpret_cast<const float4*>(
                        emb + (long long)r[k] * D + lane * 4);
            }
#pragma unroll
            for (int k = 0; k < 8; k++) {
                if (r[k] >= 0) {
                    acc.x += e[k].x; acc.y += e[k].y;
                    acc.z += e[k].z; acc.w += e[k].w;
                }
            }
        }
        __syncthreads();
    }

    // ---- flush: warp w owns the full 128-wide row of class cls0+w ----
    float* dst = &g_sums[(cls0 + w) * D + lane * 4];
    atomicAdd(dst + 0, acc.x);
    atomicAdd(dst + 1, acc.y);
    atomicAdd(dst + 2, acc.z);
    atomicAdd(dst + 3, acc.w);
    if (lane == 0) atomicAdd(&g_counts[cls0 + w], cnt);
}

// ---------------- centroids + normalized centroids ----------------
__global__ void cent_kernel() {
    const int c = blockIdx.x, t = threadIdx.x;  // 100 blocks x 128 threads
    float cntv = g_counts[c];
    float v = 0.f;
    if (cntv > 0.f) v = g_sums[c * D + t] / fmaxf(cntv, 1.f);
    g_cent[c * D + t] = v;
    float s = v * v;
#pragma unroll
    for (int o = 16; o; o >>= 1) s += __shfl_xor_sync(0xffffffffu, s, o);
    __shared__ float red[4];
    if ((t & 31) == 0) red[t >> 5] = s;
    __syncthreads();
    float norm = sqrtf(red[0] + red[1] + red[2] + red[3]);
    g_centN[c * D + t] = v / fmaxf(norm, EPSF);
}

// ---------------- pass 2: per-sample ||e - centroid[label]|| (unchanged) ----
#define P2U 4
__global__ void __launch_bounds__(256) pass2_kernel(
    const float* __restrict__ emb, const int* __restrict__ labels, int N) {
    __shared__ float sspr[C];
    const int t = threadIdx.x;
    if (t < C) sspr[t] = 0.f;
    __syncthreads();

    const int lane = t & 31;
    const int warp = blockIdx.x * (blockDim.x >> 5) + (t >> 5);
    const int nw = gridDim.x * (blockDim.x >> 5);
    const long long stride = (long long)nw * P2U;

    for (long long base = warp; base < N; base += stride) {
        float acc[P2U]; int l[P2U];
#pragma unroll
        for (int p = 0; p < P2U; p++) {
            long long i = base + (long long)p * nw;
            if (i < N) {
                int lab = labels[i];
                float4 e = *reinterpret_cast<const float4*>(emb + i * (long long)D + lane * 4);
                float4 c = *reinterpret_cast<const float4*>(g_cent + lab * D + lane * 4);
                float dx = e.x - c.x, dy = e.y - c.y, dz = e.z - c.z, dw = e.w - c.w;
                acc[p] = dx * dx + dy * dy + dz * dz + dw * dw;
                l[p] = lab;
            } else { acc[p] = 0.f; l[p] = -1; }
        }
#pragma unroll
        for (int o = 16; o; o >>= 1)
#pragma unroll
            for (int p = 0; p < P2U; p++)
                acc[p] += __shfl_xor_sync(0xffffffffu, acc[p], o);
        if (lane == 0) {
#pragma unroll
            for (int p = 0; p < P2U; p++)
                if (l[p] >= 0) atomicAdd(&sspr[l[p]], sqrtf(acc[p]));
        }
    }
    __syncthreads();
    if (t < C) atomicAdd(&g_spreadsum[t], sspr[t]);
}

// ---------------- sims = centN @ centN^T (100x100x128) ----------------
__global__ void sims_kernel() {
    extern __shared__ float sc[];  // C * 129 floats (padded, conflict-free)
    const int t = threadIdx.x;     // 128
    for (int j = t; j < C * D; j += 128) {
        int r = j >> 7, k = j & 127;
        sc[r * 129 + k] = g_centN[j];
    }
    __syncthreads();
    if (t < C) {
        const float* a = sc + blockIdx.x * 129;
        const float* b = sc + t * 129;
        float a0 = 0.f, a1 = 0.f, a2 = 0.f, a3 = 0.f;
#pragma unroll
        for (int k = 0; k < D; k += 4) {
            a0 = fmaf(a[k + 0], b[k + 0], a0);
            a1 = fmaf(a[k + 1], b[k + 1], a1);
            a2 = fmaf(a[k + 2], b[k + 2], a2);
            a3 = fmaf(a[k + 3], b[k + 3], a3);
        }
        g_sims[blockIdx.x * C + t] = (a0 + a1) + (a2 + a3);
    }
}

// ---------------- final loss (1 block) ----------------
__device__ __forceinline__ float blockReduceSum(float v, float* sred) {
    int lane = threadIdx.x & 31, w = threadIdx.x >> 5;
#pragma unroll
    for (int o = 16; o; o >>= 1) v += __shfl_xor_sync(0xffffffffu, v, o);
    if (lane == 0) sred[w] = v;
    __syncthreads();
    float s = (threadIdx.x < (blockDim.x >> 5)) ? sred[threadIdx.x] : 0.f;
    if (w == 0) {
#pragma unroll
        for (int o = 16; o; o >>= 1) s += __shfl_xor_sync(0xffffffffu, s, o);
        if (lane == 0) sred[0] = s;
    }
    __syncthreads();
    float r = sred[0];
    __syncthreads();
    return r;
}

__global__ void __launch_bounds__(256) loss_kernel(
    const float* __restrict__ ref_d, const float* __restrict__ ref_a,
    const float* __restrict__ ref_s, float* __restrict__ out) {
    __shared__ float sred[32];
    __shared__ float sspread[C];
    const int t = threadIdx.x;

    if (t < C) {
        float cntv = g_counts[t];
        sspread[t] = (cntv > 0.f) ? g_spreadsum[t] / fmaxf(cntv, 1.f) : 0.f;
    }
    __syncthreads();

    float s_rd = 0.f, s_cd = 0.f;
    for (int j = t; j < C * C; j += 256) {
        s_rd += ref_d[j];
        s_cd += 1.f - g_sims[j];
    }
    float s_rs = (t < C) ? ref_s[t] : 0.f;
    float s_cs = (t < C) ? sspread[t] : 0.f;

    float tot_rd = blockReduceSum(s_rd, sred);
    float tot_cd = blockReduceSum(s_cd, sred);
    float tot_rs = blockReduceSum(s_rs, sred);
    float tot_cs = blockReduceSum(s_cs, sred);

    float inv_rd = 1.f / (tot_rd / (float)(C * C) + EPSF);
    float inv_cd = 1.f / (tot_cd / (float)(C * C) + EPSF);
    float inv_rs = 1.f / (tot_rs / (float)C + EPSF);
    float inv_cs = 1.f / (tot_cs / (float)C + EPSF);

    float dsq = 0.f, asq = 0.f;
    for (int j = t; j < C * C; j += 256) {
        float s = g_sims[j];
        float dd = (1.f - s) * inv_cd - ref_d[j] * inv_rd;
        dsq = fmaf(dd, dd, dsq);
        float da = s - ref_a[j];
        asq = fmaf(da, da, asq);
    }
    float ssq = 0.f;
    if (t < C) {
        float d = sspread[t] * inv_cs - ref_s[t] * inv_rs;
        ssq = d * d;
    }
    float tdsq = blockReduceSum(dsq, sred);
    float tasq = blockReduceSum(asq, sred);
    float tssq = blockReduceSum(ssq, sred);
    if (t == 0)
        out[0] = tdsq / (float)(C * C) + tasq / (float)(C * C)
               + 0.5f * tssq / (float)C;
}

// ---------------- launch ----------------
extern "C" void kernel_launch(void* const* d_in, const int* in_sizes, int n_in,
                              void* d_out, int out_size) {
    const float* emb    = (const float*)d_in[0];
    const int*   labels = (const int*)d_in[1];
    int k = 2;
    if (n_in >= 6 && in_sizes[2] == 1) k = 3;  // skip scalar num_classes if passed
    const float* ref_d = (const float*)d_in[k];
    const float* ref_a = (const float*)d_in[k + 1];
    const float* ref_s = (const float*)d_in[k + 2];
    const int N = in_sizes[1];

    const int SIMS_SMEM = C * 129 * (int)sizeof(float);  // 51600 B
    cudaFuncSetAttribute(sims_kernel,
                         cudaFuncAttributeMaxDynamicSharedMemorySize, SIMS_SMEM);

    zero_kernel<<<(C * D + 255) / 256, 256>>>();
    pass1_kernel<<<CHUNKS * GRPS, 128>>>(emb, labels, N);  // 2000 blocks
    cent_kernel<<<C, D>>>();
    pass2_kernel<<<1184, 256>>>(emb, labels, N);           // 8 blocks/SM x 148
    sims_kernel<<<C, 128, SIMS_SMEM>>>();
    loss_kernel<<<1, 256>>>(ref_d, ref_a, ref_s, (float*)d_out);
}

// round 12
// speedup vs baseline: 1.2273x; 1.2273x over previous
#include <cuda_runtime.h>

#define C 100
#define D 128
#define EPSF 1e-8f
#define CHUNKS 32

// ---------------- device scratch (allocation-free) ----------------
__device__ float g_sums[C * D];
__device__ float g_counts[C];
__device__ float g_spreadsum[C];
__device__ float g_cent[C * D];
__device__ float g_centN[C * D];
__device__ float g_sims[C * C];

// ---------------- zero scratch ----------------
__global__ void zero_kernel() {
    int i = blockIdx.x * blockDim.x + threadIdx.x;
    if (i < C * D) g_sums[i] = 0.f;
    if (i < C) { g_counts[i] = 0.f; g_spreadsum[i] = 0.f; }
}

// ---------------- pass 1: class-major gather (R7, best measured) ----------
// One block per (chunk, class). Labels (4MB, L2-resident) re-scanned once per
// class; each embedding row gathered exactly once into float4 REGISTER
// accumulators. emb via __ldcs (streaming) so it does not evict the labels.
__global__ void __launch_bounds__(128) pass1_kernel(
    const float* __restrict__ emb, const int* __restrict__ labels, int N) {
    __shared__ float ssum[4 * 128];
    __shared__ float scnt[4];
    const int t = threadIdx.x, w = t >> 5, lane = t & 31;
    const int cls = blockIdx.x % C;        // consecutive bids share a chunk
    const int chunk = blockIdx.x / C;      // -> label range L1/L2-hot
    const int n_per = (N + CHUNKS - 1) / CHUNKS;
    const int start = chunk * n_per;
    const int end = min(start + n_per, N);

    float4 acc = make_float4(0.f, 0.f, 0.f, 0.f);
    float cnt = 0.f;

    for (int tb = start + w * 128; tb < end; tb += 4 * 128) {
        int lab[4];
#pragma unroll
        for (int q = 0; q < 4; q++) {
            int idx = tb + q * 32 + lane;
            lab[q] = (idx < end) ? labels[idx] : -1;
        }
#pragma unroll
        for (int q = 0; q < 4; q++) {
            unsigned m = __ballot_sync(0xffffffffu, lab[q] == cls);
            cnt += (float)__popc(m);
            while (m) {
                int j = __ffs(m) - 1;
                m &= m - 1;
                long long row = (long long)(tb + q * 32 + j);
                float4 e = __ldcs(reinterpret_cast<const float4*>(
                    emb + row * (long long)D + lane * 4));
                acc.x += e.x; acc.y += e.y; acc.z += e.z; acc.w += e.w;
            }
        }
    }

    // block reduce the 4 warp-partials, flush with spread atomics
    reinterpret_cast<float4*>(ssum)[w * 32 + lane] = acc;
    if (lane == 0) scnt[w] = cnt;
    __syncthreads();
    float s = ssum[t] + ssum[128 + t] + ssum[256 + t] + ssum[384 + t];
    atomicAdd(&g_sums[cls * D + t], s);
    if (t == 0)
        atomicAdd(&g_counts[cls], scnt[0] + scnt[1] + scnt[2] + scnt[3]);
}

// ---------------- centroids + normalized centroids ----------------
__global__ void cent_kernel() {
    const int c = blockIdx.x, t = threadIdx.x;  // 100 blocks x 128 threads
    float cntv = g_counts[c];
    float v = 0.f;
    if (cntv > 0.f) v = g_sums[c * D + t] / fmaxf(cntv, 1.f);
    g_cent[c * D + t] = v;
    float s = v * v;
#pragma unroll
    for (int o = 16; o; o >>= 1) s += __shfl_xor_sync(0xffffffffu, s, o);
    __shared__ float red[4];
    if ((t & 31) == 0) red[t >> 5] = s;
    __syncthreads();
    float norm = sqrtf(red[0] + red[1] + red[2] + red[3]);
    g_centN[c * D + t] = v / fmaxf(norm, EPSF);
}

// ---------------- pass 2: per-sample ||e - centroid[label]|| --------------
// Class accumulation in REGISTERS, no smem atomics (the old per-sample
// atomicAdd was the binding resource: ~30cyc * 6757/SM ~= 113us ~= measured).
// Class c -> (lane c&31, reg c>>5): per row ~8 predicated FADDs, 0 mem ops.
#define P2U 4
__global__ void __launch_bounds__(256) pass2_kernel(
    const float* __restrict__ emb, const int* __restrict__ labels, int N) {
    __shared__ float sacc[8][128];       // per-warp private class partials
    const int t = threadIdx.x;
    const int lane = t & 31, w = t >> 5;

    const int warp = blockIdx.x * 8 + w;
    const int nw = gridDim.x * 8;
    const long long stride = (long long)nw * P2U;

    float r0 = 0.f, r1 = 0.f, r2 = 0.f, r3 = 0.f;

    for (long long base = warp; base < N; base += stride) {
        float acc[P2U]; int l[P2U];
#pragma unroll
        for (int p = 0; p < P2U; p++) {
            long long i = base + (long long)p * nw;
            if (i < N) {
                int lab = labels[i];
                float4 e = __ldcs(reinterpret_cast<const float4*>(
                    emb + i * (long long)D + lane * 4));
                float4 c = *reinterpret_cast<const float4*>(g_cent + lab * D + lane * 4);
                float dx = e.x - c.x, dy = e.y - c.y, dz = e.z - c.z, dw = e.w - c.w;
                acc[p] = dx * dx + dy * dy + dz * dz + dw * dw;
                l[p] = lab;
            } else { acc[p] = 0.f; l[p] = -1; }
        }
#pragma unroll
        for (int o = 16; o; o >>= 1)
#pragma unroll
            for (int p = 0; p < P2U; p++)
                acc[p] += __shfl_xor_sync(0xffffffffu, acc[p], o);
#pragma unroll
        for (int p = 0; p < P2U; p++) {
            if (l[p] >= 0) {
                float dev = sqrtf(acc[p]);            // all lanes hold the sum
                int tl = l[p] & 31, ri = l[p] >> 5;
                float v = (lane == tl) ? dev : 0.f;
                r0 += (ri == 0) ? v : 0.f;
                r1 += (ri == 1) ? v : 0.f;
                r2 += (ri == 2) ? v : 0.f;
                r3 += (ri == 3) ? v : 0.f;
            }
        }
    }

    // epilogue: warp-private smem rows (no race), block reduce, 1 atomic/class
    sacc[w][lane]      = r0;
    sacc[w][32 + lane] = r1;
    sacc[w][64 + lane] = r2;
    sacc[w][96 + lane] = r3;
    __syncthreads();
    if (t < 128) {
        float s = 0.f;
#pragma unroll
        for (int ww = 0; ww < 8; ww++) s += sacc[ww][t];
        if (t < C) atomicAdd(&g_spreadsum[t], s);
    }
}

// ---------------- sims = centN @ centN^T (100x100x128) ----------------
__global__ void sims_kernel() {
    extern __shared__ float sc[];  // C * 129 floats (padded, conflict-free)
    const int t = threadIdx.x;     // 128
    for (int j = t; j < C * D; j += 128) {
        int r = j >> 7, k = j & 127;
        sc[r * 129 + k] = g_centN[j];
    }
    __syncthreads();
    if (t < C) {
        const float* a = sc + blockIdx.x * 129;
        const float* b = sc + t * 129;
        float a0 = 0.f, a1 = 0.f, a2 = 0.f, a3 = 0.f;
#pragma unroll
        for (int k = 0; k < D; k += 4) {
            a0 = fmaf(a[k + 0], b[k + 0], a0);
            a1 = fmaf(a[k + 1], b[k + 1], a1);
            a2 = fmaf(a[k + 2], b[k + 2], a2);
            a3 = fmaf(a[k + 3], b[k + 3], a3);
        }
        g_sims[blockIdx.x * C + t] = (a0 + a1) + (a2 + a3);
    }
}

// ---------------- final loss (1 block) ----------------
__device__ __forceinline__ float blockReduceSum(float v, float* sred) {
    int lane = threadIdx.x & 31, w = threadIdx.x >> 5;
#pragma unroll
    for (int o = 16; o; o >>= 1) v += __shfl_xor_sync(0xffffffffu, v, o);
    if (lane == 0) sred[w] = v;
    __syncthreads();
    float s = (threadIdx.x < (blockDim.x >> 5)) ? sred[threadIdx.x] : 0.f;
    if (w == 0) {
#pragma unroll
        for (int o = 16; o; o >>= 1) s += __shfl_xor_sync(0xffffffffu, s, o);
        if (lane == 0) sred[0] = s;
    }
    __syncthreads();
    float r = sred[0];
    __syncthreads();
    return r;
}

__global__ void __launch_bounds__(256) loss_kernel(
    const float* __restrict__ ref_d, const float* __restrict__ ref_a,
    const float* __restrict__ ref_s, float* __restrict__ out) {
    __shared__ float sred[32];
    __shared__ float sspread[C];
    const int t = threadIdx.x;

    if (t < C) {
        float cntv = g_counts[t];
        sspread[t] = (cntv > 0.f) ? g_spreadsum[t] / fmaxf(cntv, 1.f) : 0.f;
    }
    __syncthreads();

    float s_rd = 0.f, s_cd = 0.f;
    for (int j = t; j < C * C; j += 256) {
        s_rd += ref_d[j];
        s_cd += 1.f - g_sims[j];
    }
    float s_rs = (t < C) ? ref_s[t] : 0.f;
    float s_cs = (t < C) ? sspread[t] : 0.f;

    float tot_rd = blockReduceSum(s_rd, sred);
    float tot_cd = blockReduceSum(s_cd, sred);
    float tot_rs = blockReduceSum(s_rs, sred);
    float tot_cs = blockReduceSum(s_cs, sred);

    float inv_rd = 1.f / (tot_rd / (float)(C * C) + EPSF);
    float inv_cd = 1.f / (tot_cd / (float)(C * C) + EPSF);
    float inv_rs = 1.f / (tot_rs / (float)C + EPSF);
    float inv_cs = 1.f / (tot_cs / (float)C + EPSF);

    float dsq = 0.f, asq = 0.f;
    for (int j = t; j < C * C; j += 256) {
        float s = g_sims[j];
        float dd = (1.f - s) * inv_cd - ref_d[j] * inv_rd;
        dsq = fmaf(dd, dd, dsq);
        float da = s - ref_a[j];
        asq = fmaf(da, da, asq);
    }
    float ssq = 0.f;
    if (t < C) {
        float d = sspread[t] * inv_cs - ref_s[t] * inv_rs;
        ssq = d * d;
    }
    float tdsq = blockReduceSum(dsq, sred);
    float tasq = blockReduceSum(asq, sred);
    float tssq = blockReduceSum(ssq, sred);
    if (t == 0)
        out[0] = tdsq / (float)(C * C) + tasq / (float)(C * C)
               + 0.5f * tssq / (float)C;
}

// ---------------- launch ----------------
extern "C" void kernel_launch(void* const* d_in, const int* in_sizes, int n_in,
                              void* d_out, int out_size) {
    const float* emb    = (const float*)d_in[0];
    const int*   labels = (const int*)d_in[1];
    int k = 2;
    if (n_in >= 6 && in_sizes[2] == 1) k = 3;  // skip scalar num_classes if passed
    const float* ref_d = (const float*)d_in[k];
    const float* ref_a = (const float*)d_in[k + 1];
    const float* ref_s = (const float*)d_in[k + 2];
    const int N = in_sizes[1];

    const int SIMS_SMEM = C * 129 * (int)sizeof(float);  // 51600 B
    cudaFuncSetAttribute(sims_kernel,
                         cudaFuncAttributeMaxDynamicSharedMemorySize, SIMS_SMEM);

    zero_kernel<<<(C * D + 255) / 256, 256>>>();
    pass1_kernel<<<CHUNKS * C, 128>>>(emb, labels, N);   // 3200 blocks (R7)
    cent_kernel<<<C, D>>>();
    pass2_kernel<<<1184, 256>>>(emb, labels, N);         // 8 blocks/SM x 148
    sims_kernel<<<C, 128, SIMS_SMEM>>>();
    loss_kernel<<<1, 256>>>(ref_d, ref_a, ref_s, (float*)d_out);
}